// round 16
// baseline (speedup 1.0000x reference)
#include <cuda_runtime.h>
#include <cuda_fp16.h>
#include <cstdint>
#include <math.h>

// Problem constants
#define S_LEN 4096
#define E_DIM 1024
#define E3    3072
#define NHEAD 16
#define HDIM  64
#define QBLK  128

// ---------------------------------------------------------------------------
// Scratch (device globals; allocation is forbidden)
// ---------------------------------------------------------------------------
__device__ __half g_qkvhi[S_LEN * E3];
__device__ __half g_xhi[S_LEN * E_DIM];
__device__ __half g_w1hi[E3 * E_DIM];
__device__ __half g_w2hi[E_DIM * E_DIM];
__device__ __half g_chi[S_LEN * E_DIM];

// ---------------------------------------------------------------------------
// Helpers
// ---------------------------------------------------------------------------
__device__ __forceinline__ uint32_t smem_u32(const void* p) {
    uint32_t a;
    asm("{ .reg .u64 t; cvta.to.shared.u64 t, %1; cvt.u32.u64 %0, t; }"
        : "=r"(a) : "l"(p));
    return a;
}
__device__ __forceinline__ void ldsm4(uint32_t r[4], uint32_t addr) {
    asm volatile("ldmatrix.sync.aligned.m8n8.x4.shared.b16 {%0,%1,%2,%3}, [%4];"
                 : "=r"(r[0]), "=r"(r[1]), "=r"(r[2]), "=r"(r[3]) : "r"(addr));
}
__device__ __forceinline__ void ldsm4t(uint32_t r[4], uint32_t addr) {
    asm volatile("ldmatrix.sync.aligned.m8n8.x4.trans.shared.b16 {%0,%1,%2,%3}, [%4];"
                 : "=r"(r[0]), "=r"(r[1]), "=r"(r[2]), "=r"(r[3]) : "r"(addr));
}
__device__ __forceinline__ void mma_f16(float c[4], const uint32_t a[4],
                                        const uint32_t b[2]) {
    asm volatile("mma.sync.aligned.m16n8k16.row.col.f32.f16.f16.f32 "
                 "{%0,%1,%2,%3}, {%4,%5,%6,%7}, {%8,%9}, {%0,%1,%2,%3};"
                 : "+f"(c[0]), "+f"(c[1]), "+f"(c[2]), "+f"(c[3])
                 : "r"(a[0]), "r"(a[1]), "r"(a[2]), "r"(a[3]),
                   "r"(b[0]), "r"(b[1]));
}
__device__ __forceinline__ float ex2f(float x) {
    float r; asm("ex2.approx.f32 %0, %1;" : "=f"(r) : "f"(x)); return r;
}
// pack {lo=a, hi=b} as f16x2
__device__ __forceinline__ uint32_t pack_h2(float a, float b) {
    uint32_t d;
    asm("cvt.rn.f16x2.f32 %0, %1, %2;" : "=r"(d) : "f"(b), "f"(a));
    return d;
}

// ---------------------------------------------------------------------------
// Fused fp32 -> fp16 convert for all three inputs
// ---------------------------------------------------------------------------
#define NX  (S_LEN * E_DIM)
#define NW1 (E3 * E_DIM)
#define NW2 (E_DIM * E_DIM)

__global__ void convert_all_kernel(const float* __restrict__ x,
                                   const float* __restrict__ w1,
                                   const float* __restrict__ w2,
                                   __half* __restrict__ xhi,
                                   __half* __restrict__ w1hi,
                                   __half* __restrict__ w2hi)
{
    int i = (blockIdx.x * blockDim.x + threadIdx.x) * 4;
    const float* src;
    __half* dst;
    int j;
    if (i < NX) { src = x; dst = xhi; j = i; }
    else if (i < NX + NW1) { src = w1; dst = w1hi; j = i - NX; }
    else if (i < NX + NW1 + NW2) { src = w2; dst = w2hi; j = i - NX - NW1; }
    else return;
    float4 v = *(const float4*)(src + j);
    *(__half2*)(dst + j)     = __halves2half2(__float2half_rn(v.x), __float2half_rn(v.y));
    *(__half2*)(dst + j + 2) = __halves2half2(__float2half_rn(v.z), __float2half_rn(v.w));
}

// ---------------------------------------------------------------------------
// mma.sync fp16 GEMM (1 product): C[M,N] = A[M,K] @ B[N,K]^T + bias[N]
// CTA 128x128, 8 warps 2(m)x4(n), KC=64 (16 chunks for K=1024),
// 2-stage cp.async, 2 CTAs/SM. Rows padded to 144B (conflict-free ldsm).
// HALFOUT: output fp16, q-scale applied on cols < qcols.
// ---------------------------------------------------------------------------
#define KC 64
#define ROWB 144
#define MATB (128 * ROWB)        // 18432
#define STAGEB (2 * MATB)        // A, B: 36864
#define GEMM_SMEM (2 * STAGEB)   // 73728

template<bool HALFOUT>
__global__ __launch_bounds__(256, 2) void gemm_mma(
    const __half* __restrict__ A, const __half* __restrict__ B,
    const float* __restrict__ bias,
    float* __restrict__ Cf, __half* __restrict__ Ch,
    int M, int N, int K, int qcols, float qscale)
{
    extern __shared__ char smem[];
    const uint32_t sb = smem_u32(smem);
    const int tid = threadIdx.x;
    const int lane = tid & 31;
    const int wid = tid >> 5;
    const int wm = wid & 1;
    const int wn = wid >> 1;
    const int bm = blockIdx.y * 128;
    const int bn = blockIdx.x * 128;

    // copy mapping: thread -> (row = tid>>1, 64B half = tid&1)
    const int cr = tid >> 1;
    const int chalf = tid & 1;

    const __half* srcA = A + (size_t)(bm + cr) * K;
    const __half* srcB = B + (size_t)(bn + cr) * K;

    auto copy_stage = [&](int c, int buf) {
        uint32_t dst = sb + buf * STAGEB + cr * ROWB + chalf * 64;
        size_t soff = (size_t)c * (KC * 2) + chalf * 64;
        {
            const char* sp = (const char*)srcA + soff;
            asm volatile("cp.async.cg.shared.global [%0], [%1], 16;" :: "r"(dst), "l"(sp));
            asm volatile("cp.async.cg.shared.global [%0], [%1], 16;" :: "r"(dst + 16), "l"(sp + 16));
            asm volatile("cp.async.cg.shared.global [%0], [%1], 16;" :: "r"(dst + 32), "l"(sp + 32));
            asm volatile("cp.async.cg.shared.global [%0], [%1], 16;" :: "r"(dst + 48), "l"(sp + 48));
        }
        {
            const char* sp = (const char*)srcB + soff;
            uint32_t dp = dst + MATB;
            asm volatile("cp.async.cg.shared.global [%0], [%1], 16;" :: "r"(dp), "l"(sp));
            asm volatile("cp.async.cg.shared.global [%0], [%1], 16;" :: "r"(dp + 16), "l"(sp + 16));
            asm volatile("cp.async.cg.shared.global [%0], [%1], 16;" :: "r"(dp + 32), "l"(sp + 32));
            asm volatile("cp.async.cg.shared.global [%0], [%1], 16;" :: "r"(dp + 48), "l"(sp + 48));
        }
    };

    const uint32_t aoff = (uint32_t)((wm * 64 + (lane & 15)) * ROWB + (lane >> 4) * 16);
    const uint32_t boff = (uint32_t)((wn * 32 + ((lane >> 4) << 3) + (lane & 7)) * ROWB
                                     + ((lane >> 3) & 1) * 16);

    float acc[4][4][4];
#pragma unroll
    for (int mt = 0; mt < 4; mt++)
#pragma unroll
        for (int nt = 0; nt < 4; nt++)
#pragma unroll
            for (int e = 0; e < 4; e++) acc[mt][nt][e] = 0.f;

    const int NC = K / KC;
    copy_stage(0, 0);
    asm volatile("cp.async.commit_group;");
    copy_stage(1, 1);
    asm volatile("cp.async.commit_group;");

    for (int c = 0; c < NC; ++c) {
        if (c + 1 < NC) asm volatile("cp.async.wait_group 1;");
        else            asm volatile("cp.async.wait_group 0;");
        __syncthreads();

        const uint32_t sbase = sb + (c & 1) * STAGEB;
        const uint32_t aB = sbase + aoff;
        const uint32_t bB = sbase + MATB + boff;

#pragma unroll
        for (int ks = 0; ks < 4; ++ks) {
            uint32_t bh[8];
            ldsm4(bh,     bB + ks * 32);
            ldsm4(bh + 4, bB + 16 * ROWB + ks * 32);
#pragma unroll
            for (int mt = 0; mt < 4; ++mt) {
                uint32_t ah[4];
                ldsm4(ah, aB + mt * (16 * ROWB) + ks * 32);
#pragma unroll
                for (int nt = 0; nt < 4; ++nt) mma_f16(acc[mt][nt], ah, &bh[nt * 2]);
            }
        }
        if (c + 2 < NC) {
            __syncthreads();
            copy_stage(c + 2, c & 1);
            asm volatile("cp.async.commit_group;");
        }
    }

    const int g = lane >> 2;
    const int t2 = (lane & 3) * 2;
#pragma unroll
    for (int mt = 0; mt < 4; ++mt) {
        int row0 = bm + wm * 64 + mt * 16 + g;
#pragma unroll
        for (int nt = 0; nt < 4; ++nt) {
            int col = bn + wn * 32 + nt * 8 + t2;
            float2 b2 = *(const float2*)&bias[col];
            float f00 = acc[mt][nt][0] + b2.x, f01 = acc[mt][nt][1] + b2.y;
            float f10 = acc[mt][nt][2] + b2.x, f11 = acc[mt][nt][3] + b2.y;
            if (HALFOUT) {
                if (col < qcols) { f00 *= qscale; f01 *= qscale; f10 *= qscale; f11 *= qscale; }
                *(__half2*)(Ch + (size_t)row0 * N + col) =
                    __halves2half2(__float2half_rn(f00), __float2half_rn(f01));
                *(__half2*)(Ch + (size_t)(row0 + 8) * N + col) =
                    __halves2half2(__float2half_rn(f10), __float2half_rn(f11));
            } else {
                *(float2*)(Cf + (size_t)row0 * N + col) = make_float2(f00, f01);
                *(float2*)(Cf + (size_t)(row0 + 8) * N + col) = make_float2(f10, f11);
            }
        }
    }
}

// ---------------------------------------------------------------------------
// MMA flash attention (fp16; all operands single-term).
// Full 128-key tiles, double-buffered cp.async KV, 1 CTA/SM.
// softmax log2-domain (q pre-scaled by 0.125*log2e in QKV epilogue).
// ---------------------------------------------------------------------------
#define AT_ROWB 144
#define AT_MAT  (128 * AT_ROWB)        // 18432
#define KVSTG   (2 * AT_MAT)           // Kh + Vh
#define OFF_Q   0
#define OFF_ST  AT_MAT
#define ATTN_SMEM (OFF_ST + 2 * KVSTG) // 92160

__global__ __launch_bounds__(256, 1) void attn_mma(
    const __half* __restrict__ qkvhi, __half* __restrict__ chi)
{
    extern __shared__ char smc[];
    const uint32_t sb = smem_u32(smc);
    const int tid = threadIdx.x;
    const int lane = tid & 31;
    const int wm = tid >> 5;
    const int h = blockIdx.y;
    const int qb = 31 - (int)blockIdx.x;
    const int qrow0 = qb * QBLK;

    // A-operand lane map (Q, and V rows for ldmatrix.trans)
    const int grp = lane >> 3;
    const int rbase = (lane & 7) + ((grp & 1) << 3);
    const uint32_t cbase = (uint32_t)((grp >> 1) << 4);
    // B-operand lane map (K)
    const int krow = ((lane >> 4) << 3) + (lane & 7);
    const uint32_t kcol = (uint32_t)(((lane >> 3) & 1) * 16);

    // ---- issue Q + tile0 loads ----
    {
#pragma unroll
        for (int i = 0; i < 4; i++) {
            int id = tid + i * 256;
            int row = id >> 3, col = id & 7;
            uint32_t d = sb + OFF_Q + row * AT_ROWB + col * 16;
            size_t gq = (size_t)(qrow0 + row) * E3 + h * HDIM + col * 8;
            asm volatile("cp.async.cg.shared.global [%0], [%1], 16;"
                         :: "r"(d), "l"((const char*)(qkvhi + gq)));
        }
    }
    auto load_kv = [&](int j, int st) {
        uint32_t stb = sb + OFF_ST + st * KVSTG;
#pragma unroll
        for (int i = 0; i < 4; i++) {
            int id = tid + i * 256;
            int row = id >> 3, col = id & 7;
            uint32_t d = stb + row * AT_ROWB + col * 16;
            size_t gk = (size_t)(j * QBLK + row) * E3 + E_DIM + h * HDIM + col * 8;
            size_t gv = gk + E_DIM;
            asm volatile("cp.async.cg.shared.global [%0], [%1], 16;"
                         :: "r"(d), "l"((const char*)(qkvhi + gk)));
            asm volatile("cp.async.cg.shared.global [%0], [%1], 16;"
                         :: "r"(d + AT_MAT), "l"((const char*)(qkvhi + gv)));
        }
    };
    load_kv(0, 0);
    asm volatile("cp.async.commit_group;");
    asm volatile("cp.async.wait_group 0;");
    __syncthreads();

    // ---- Q fragments (persistent) ----
    uint32_t qh[4][4];
    {
        uint32_t qaddr = sb + OFF_Q + (wm * 16 + rbase) * AT_ROWB + cbase;
#pragma unroll
        for (int kt = 0; kt < 4; kt++)
            ldsm4(qh[kt], qaddr + kt * 32);
    }

    float o[8][4];
#pragma unroll
    for (int nt = 0; nt < 8; nt++)
#pragma unroll
        for (int e = 0; e < 4; e++) o[nt][e] = 0.f;
    float m0 = -1e30f, m1 = -1e30f, l0 = 0.f, l1 = 0.f;

    for (int j = 0; j <= qb; ++j) {
        if (j > 0) {
            asm volatile("cp.async.wait_group 0;");
        }
        __syncthreads();
        if (j < qb) {
            load_kv(j + 1, (j + 1) & 1);
            asm volatile("cp.async.commit_group;");
        }
        const uint32_t stb = sb + OFF_ST + (j & 1) * KVSTG;

        // ---- S = Q @ K^T (1 product) ----
        float c[16][4];
#pragma unroll
        for (int nt = 0; nt < 16; nt++)
#pragma unroll
            for (int e = 0; e < 4; e++) c[nt][e] = 0.f;

#pragma unroll
        for (int kt = 0; kt < 4; kt++) {
#pragma unroll
            for (int P = 0; P < 8; P++) {
                uint32_t ka = stb + (P * 16 + krow) * AT_ROWB + kt * 32 + kcol;
                uint32_t kh[4];
                ldsm4(kh, ka);
                mma_f16(c[2 * P],     qh[kt], &kh[0]);
                mma_f16(c[2 * P + 1], qh[kt], &kh[2]);
            }
        }

        // ---- online softmax (log2 domain) ----
        float mx0 = c[0][0], mx1 = c[0][2];
#pragma unroll
        for (int nt = 0; nt < 16; nt++) {
            mx0 = fmaxf(mx0, fmaxf(c[nt][0], c[nt][1]));
            mx1 = fmaxf(mx1, fmaxf(c[nt][2], c[nt][3]));
        }
#pragma unroll
        for (int off = 1; off < 4; off <<= 1) {
            mx0 = fmaxf(mx0, __shfl_xor_sync(0xffffffffu, mx0, off));
            mx1 = fmaxf(mx1, __shfl_xor_sync(0xffffffffu, mx1, off));
        }
        float mn0 = fmaxf(m0, mx0), mn1 = fmaxf(m1, mx1);
        float a0 = ex2f(m0 - mn0), a1 = ex2f(m1 - mn1);
        m0 = mn0; m1 = mn1;
        float s0 = 0.f, s1 = 0.f;
#pragma unroll
        for (int nt = 0; nt < 16; nt++) {
            c[nt][0] = ex2f(c[nt][0] - mn0);
            c[nt][1] = ex2f(c[nt][1] - mn0);
            c[nt][2] = ex2f(c[nt][2] - mn1);
            c[nt][3] = ex2f(c[nt][3] - mn1);
            s0 += c[nt][0] + c[nt][1];
            s1 += c[nt][2] + c[nt][3];
        }
#pragma unroll
        for (int off = 1; off < 4; off <<= 1) {
            s0 += __shfl_xor_sync(0xffffffffu, s0, off);
            s1 += __shfl_xor_sync(0xffffffffu, s1, off);
        }
        l0 = l0 * a0 + s0;
        l1 = l1 * a1 + s1;
#pragma unroll
        for (int nt = 0; nt < 8; nt++) {
            o[nt][0] *= a0; o[nt][1] *= a0;
            o[nt][2] *= a1; o[nt][3] *= a1;
        }

        // ---- O += P @ V (single-term) ----
#pragma unroll
        for (int J = 0; J < 8; J++) {
            uint32_t phi[4];
#pragma unroll
            for (int q4 = 0; q4 < 2; q4++) {
#pragma unroll
                for (int rh = 0; rh < 2; rh++) {
                    phi[q4 * 2 + rh] = pack_h2(c[2 * J + q4][2 * rh],
                                               c[2 * J + q4][2 * rh + 1]);
                }
            }
#pragma unroll
            for (int pr = 0; pr < 4; pr++) {
                uint32_t va = stb + AT_MAT + (J * 16 + rbase) * AT_ROWB
                              + pr * 32 + cbase;
                uint32_t vh[4];
                ldsm4t(vh, va);
                mma_f16(o[2 * pr],     phi, &vh[0]);
                mma_f16(o[2 * pr + 1], phi, &vh[2]);
            }
        }
    }

    // ---- epilogue: normalize, fp16 ctx ----
    float inv0 = 1.f / l0, inv1 = 1.f / l1;
    const int g = lane >> 2;
    const int cp2 = (lane & 3) * 2;
    int row0 = qrow0 + wm * 16 + g;
#pragma unroll
    for (int nt = 0; nt < 8; nt++) {
        int col = h * HDIM + nt * 8 + cp2;
        *(__half2*)(chi + (size_t)row0 * E_DIM + col) =
            __halves2half2(__float2half_rn(o[nt][0] * inv0),
                           __float2half_rn(o[nt][1] * inv0));
        *(__half2*)(chi + (size_t)(row0 + 8) * E_DIM + col) =
            __halves2half2(__float2half_rn(o[nt][2] * inv1),
                           __float2half_rn(o[nt][3] * inv1));
    }
}

// ---------------------------------------------------------------------------
extern "C" void kernel_launch(void* const* d_in, const int* in_sizes, int n_in,
                              void* d_out, int out_size)
{
    const float* x     = (const float*)d_in[0];
    const float* w_in  = (const float*)d_in[1];
    const float* b_in  = (const float*)d_in[2];
    const float* w_out = (const float*)d_in[3];
    const float* b_out = (const float*)d_in[4];
    float* out = (float*)d_out;

    __half *qkvhi, *xhi, *w1hi, *w2hi, *chi;
    cudaGetSymbolAddress((void**)&qkvhi, g_qkvhi);
    cudaGetSymbolAddress((void**)&xhi,  g_xhi);
    cudaGetSymbolAddress((void**)&w1hi, g_w1hi);
    cudaGetSymbolAddress((void**)&w2hi, g_w2hi);
    cudaGetSymbolAddress((void**)&chi,  g_chi);

    cudaFuncSetAttribute((const void*)gemm_mma<true>,
                         cudaFuncAttributeMaxDynamicSharedMemorySize, GEMM_SMEM);
    cudaFuncSetAttribute((const void*)gemm_mma<false>,
                         cudaFuncAttributeMaxDynamicSharedMemorySize, GEMM_SMEM);
    cudaFuncSetAttribute(attn_mma, cudaFuncAttributeMaxDynamicSharedMemorySize, ATTN_SMEM);

    // 0) fused fp32 -> fp16 converts
    {
        int total = NX + NW1 + NW2;
        convert_all_kernel<<<(total / 4 + 255) / 256, 256>>>(x, w_in, w_out,
                                                             xhi, w1hi, w2hi);
    }

    const float qscale = 0.125f * 1.44269504088896340736f;  // (1/sqrt(64))*log2(e)

    // 1) QKV projection (1-product fp16, KC=64) -> fp16 qkv (q cols pre-scaled)
    {
        dim3 grid(E3 / 128, S_LEN / 128);
        gemm_mma<true><<<grid, 256, GEMM_SMEM>>>(xhi, w1hi, b_in,
                                                 nullptr, qkvhi,
                                                 S_LEN, E3, E_DIM, E_DIM, qscale);
    }

    // 2) block-causal attention -> ctx fp16
    {
        dim3 grid(S_LEN / QBLK, NHEAD);
        attn_mma<<<grid, 256, ATTN_SMEM>>>(qkvhi, chi);
    }

    // 3) out projection (1-product fp16, KC=64) -> fp32 out
    {
        dim3 grid(E_DIM / 128, S_LEN / 128);
        gemm_mma<false><<<grid, 256, GEMM_SMEM>>>(chi, w2hi, b_out,
                                                  out, nullptr,
                                                  S_LEN, E_DIM, E_DIM, 0, 1.0f);
    }
}

// round 17
// speedup vs baseline: 1.0753x; 1.0753x over previous
#include <cuda_runtime.h>
#include <cuda_fp16.h>
#include <cstdint>
#include <math.h>

// Problem constants
#define S_LEN 4096
#define E_DIM 1024
#define E3    3072
#define NHEAD 16
#define HDIM  64
#define QBLK  128

// ---------------------------------------------------------------------------
// Scratch (device globals; allocation is forbidden)
// ---------------------------------------------------------------------------
__device__ __half g_qkvhi[S_LEN * E3];
__device__ __half g_xhi[S_LEN * E_DIM];
__device__ __half g_w1hi[E3 * E_DIM];
__device__ __half g_w2hi[E_DIM * E_DIM];
__device__ __half g_chi[S_LEN * E_DIM];

// ---------------------------------------------------------------------------
// Helpers
// ---------------------------------------------------------------------------
__device__ __forceinline__ uint32_t smem_u32(const void* p) {
    uint32_t a;
    asm("{ .reg .u64 t; cvta.to.shared.u64 t, %1; cvt.u32.u64 %0, t; }"
        : "=r"(a) : "l"(p));
    return a;
}
__device__ __forceinline__ void ldsm4(uint32_t r[4], uint32_t addr) {
    asm volatile("ldmatrix.sync.aligned.m8n8.x4.shared.b16 {%0,%1,%2,%3}, [%4];"
                 : "=r"(r[0]), "=r"(r[1]), "=r"(r[2]), "=r"(r[3]) : "r"(addr));
}
__device__ __forceinline__ void ldsm4t(uint32_t r[4], uint32_t addr) {
    asm volatile("ldmatrix.sync.aligned.m8n8.x4.trans.shared.b16 {%0,%1,%2,%3}, [%4];"
                 : "=r"(r[0]), "=r"(r[1]), "=r"(r[2]), "=r"(r[3]) : "r"(addr));
}
__device__ __forceinline__ void mma_f16(float c[4], const uint32_t a[4],
                                        const uint32_t b[2]) {
    asm volatile("mma.sync.aligned.m16n8k16.row.col.f32.f16.f16.f32 "
                 "{%0,%1,%2,%3}, {%4,%5,%6,%7}, {%8,%9}, {%0,%1,%2,%3};"
                 : "+f"(c[0]), "+f"(c[1]), "+f"(c[2]), "+f"(c[3])
                 : "r"(a[0]), "r"(a[1]), "r"(a[2]), "r"(a[3]),
                   "r"(b[0]), "r"(b[1]));
}
__device__ __forceinline__ float ex2f(float x) {
    float r; asm("ex2.approx.f32 %0, %1;" : "=f"(r) : "f"(x)); return r;
}
// pack {lo=a, hi=b} as f16x2
__device__ __forceinline__ uint32_t pack_h2(float a, float b) {
    uint32_t d;
    asm("cvt.rn.f16x2.f32 %0, %1, %2;" : "=r"(d) : "f"(b), "f"(a));
    return d;
}

// ---------------------------------------------------------------------------
// Fused fp32 -> fp16 convert for all three inputs
// ---------------------------------------------------------------------------
#define NX  (S_LEN * E_DIM)
#define NW1 (E3 * E_DIM)
#define NW2 (E_DIM * E_DIM)

__global__ void convert_all_kernel(const float* __restrict__ x,
                                   const float* __restrict__ w1,
                                   const float* __restrict__ w2,
                                   __half* __restrict__ xhi,
                                   __half* __restrict__ w1hi,
                                   __half* __restrict__ w2hi)
{
    int i = (blockIdx.x * blockDim.x + threadIdx.x) * 4;
    const float* src;
    __half* dst;
    int j;
    if (i < NX) { src = x; dst = xhi; j = i; }
    else if (i < NX + NW1) { src = w1; dst = w1hi; j = i - NX; }
    else if (i < NX + NW1 + NW2) { src = w2; dst = w2hi; j = i - NX - NW1; }
    else return;
    float4 v = *(const float4*)(src + j);
    *(__half2*)(dst + j)     = __halves2half2(__float2half_rn(v.x), __float2half_rn(v.y));
    *(__half2*)(dst + j + 2) = __halves2half2(__float2half_rn(v.z), __float2half_rn(v.w));
}

// ---------------------------------------------------------------------------
// mma.sync fp16 GEMM (1 product): C[M,N] = A[M,K] @ B[N,K]^T + bias[N]
// CTA 128x128, 8 warps 2(m)x4(n), KC=32, 4-stage cp.async pipeline
// (prefetch depth 3 chunks to cover L2 latency), 2 CTAs/SM.
// HALFOUT: output fp16, q-scale applied on cols < qcols.
// ---------------------------------------------------------------------------
#define KC 32
#define ROWB 80
#define MATB (128 * ROWB)        // 10240
#define STAGEB (2 * MATB)        // A, B: 20480
#define NSTAGE 4
#define GEMM_SMEM (NSTAGE * STAGEB)   // 81920

template<bool HALFOUT>
__global__ __launch_bounds__(256, 2) void gemm_mma(
    const __half* __restrict__ A, const __half* __restrict__ B,
    const float* __restrict__ bias,
    float* __restrict__ Cf, __half* __restrict__ Ch,
    int M, int N, int K, int qcols, float qscale)
{
    extern __shared__ char smem[];
    const uint32_t sb = smem_u32(smem);
    const int tid = threadIdx.x;
    const int lane = tid & 31;
    const int wid = tid >> 5;
    const int wm = wid & 1;
    const int wn = wid >> 1;
    const int bm = blockIdx.y * 128;
    const int bn = blockIdx.x * 128;

    const int cr = tid >> 1;
    const int chalf = tid & 1;

    const __half* srcA = A + (size_t)(bm + cr) * K;
    const __half* srcB = B + (size_t)(bn + cr) * K;

    auto copy_stage = [&](int c, int buf) {
        uint32_t dst = sb + buf * STAGEB + cr * ROWB + chalf * 32;
        size_t soff = (size_t)c * (KC * 2) + chalf * 32;
        {
            const char* sp = (const char*)srcA + soff;
            asm volatile("cp.async.cg.shared.global [%0], [%1], 16;" :: "r"(dst), "l"(sp));
            asm volatile("cp.async.cg.shared.global [%0], [%1], 16;" :: "r"(dst + 16), "l"(sp + 16));
        }
        {
            const char* sp = (const char*)srcB + soff;
            uint32_t dp = dst + MATB;
            asm volatile("cp.async.cg.shared.global [%0], [%1], 16;" :: "r"(dp), "l"(sp));
            asm volatile("cp.async.cg.shared.global [%0], [%1], 16;" :: "r"(dp + 16), "l"(sp + 16));
        }
    };

    const uint32_t aoff = (uint32_t)((wm * 64 + (lane & 15)) * ROWB + (lane >> 4) * 16);
    const uint32_t boff = (uint32_t)((wn * 32 + ((lane >> 4) << 3) + (lane & 7)) * ROWB
                                     + ((lane >> 3) & 1) * 16);

    float acc[4][4][4];
#pragma unroll
    for (int mt = 0; mt < 4; mt++)
#pragma unroll
        for (int nt = 0; nt < 4; nt++)
#pragma unroll
            for (int e = 0; e < 4; e++) acc[mt][nt][e] = 0.f;

    const int NC = K / KC;   // 32 or 16; always >= 3 here
    copy_stage(0, 0);
    asm volatile("cp.async.commit_group;");
    copy_stage(1, 1);
    asm volatile("cp.async.commit_group;");
    copy_stage(2, 2);
    asm volatile("cp.async.commit_group;");

    for (int c = 0; c < NC; ++c) {
        if (c + 2 < NC)      asm volatile("cp.async.wait_group 2;");
        else if (c + 1 < NC) asm volatile("cp.async.wait_group 1;");
        else                 asm volatile("cp.async.wait_group 0;");
        __syncthreads();

        const uint32_t sbase = sb + (c & 3) * STAGEB;
        const uint32_t aB = sbase + aoff;
        const uint32_t bB = sbase + MATB + boff;

#pragma unroll
        for (int ks = 0; ks < 2; ++ks) {
            uint32_t bh[8];
            ldsm4(bh,     bB + ks * 32);
            ldsm4(bh + 4, bB + 16 * ROWB + ks * 32);
#pragma unroll
            for (int mt = 0; mt < 4; ++mt) {
                uint32_t ah[4];
                ldsm4(ah, aB + mt * (16 * ROWB) + ks * 32);
#pragma unroll
                for (int nt = 0; nt < 4; ++nt) mma_f16(acc[mt][nt], ah, &bh[nt * 2]);
            }
        }
        if (c + 3 < NC) {
            copy_stage(c + 3, (c + 3) & 3);
            asm volatile("cp.async.commit_group;");
        }
    }

    const int g = lane >> 2;
    const int t2 = (lane & 3) * 2;
#pragma unroll
    for (int mt = 0; mt < 4; ++mt) {
        int row0 = bm + wm * 64 + mt * 16 + g;
#pragma unroll
        for (int nt = 0; nt < 4; ++nt) {
            int col = bn + wn * 32 + nt * 8 + t2;
            float2 b2 = *(const float2*)&bias[col];
            float f00 = acc[mt][nt][0] + b2.x, f01 = acc[mt][nt][1] + b2.y;
            float f10 = acc[mt][nt][2] + b2.x, f11 = acc[mt][nt][3] + b2.y;
            if (HALFOUT) {
                if (col < qcols) { f00 *= qscale; f01 *= qscale; f10 *= qscale; f11 *= qscale; }
                *(__half2*)(Ch + (size_t)row0 * N + col) =
                    __halves2half2(__float2half_rn(f00), __float2half_rn(f01));
                *(__half2*)(Ch + (size_t)(row0 + 8) * N + col) =
                    __halves2half2(__float2half_rn(f10), __float2half_rn(f11));
            } else {
                *(float2*)(Cf + (size_t)row0 * N + col) = make_float2(f00, f01);
                *(float2*)(Cf + (size_t)(row0 + 8) * N + col) = make_float2(f10, f11);
            }
        }
    }
}

// ---------------------------------------------------------------------------
// MMA flash attention (fp16; all operands single-term). UNCHANGED from r15.
// Full 128-key tiles, double-buffered cp.async KV, 1 CTA/SM.
// softmax log2-domain (q pre-scaled by 0.125*log2e in QKV epilogue).
// ---------------------------------------------------------------------------
#define AT_ROWB 144
#define AT_MAT  (128 * AT_ROWB)        // 18432
#define KVSTG   (2 * AT_MAT)           // Kh + Vh
#define OFF_Q   0
#define OFF_ST  AT_MAT
#define ATTN_SMEM (OFF_ST + 2 * KVSTG) // 92160

__global__ __launch_bounds__(256, 1) void attn_mma(
    const __half* __restrict__ qkvhi, __half* __restrict__ chi)
{
    extern __shared__ char smc[];
    const uint32_t sb = smem_u32(smc);
    const int tid = threadIdx.x;
    const int lane = tid & 31;
    const int wm = tid >> 5;
    const int h = blockIdx.y;
    const int qb = 31 - (int)blockIdx.x;
    const int qrow0 = qb * QBLK;

    // A-operand lane map (Q, and V rows for ldmatrix.trans)
    const int grp = lane >> 3;
    const int rbase = (lane & 7) + ((grp & 1) << 3);
    const uint32_t cbase = (uint32_t)((grp >> 1) << 4);
    // B-operand lane map (K)
    const int krow = ((lane >> 4) << 3) + (lane & 7);
    const uint32_t kcol = (uint32_t)(((lane >> 3) & 1) * 16);

    // ---- issue Q + tile0 loads ----
    {
#pragma unroll
        for (int i = 0; i < 4; i++) {
            int id = tid + i * 256;
            int row = id >> 3, col = id & 7;
            uint32_t d = sb + OFF_Q + row * AT_ROWB + col * 16;
            size_t gq = (size_t)(qrow0 + row) * E3 + h * HDIM + col * 8;
            asm volatile("cp.async.cg.shared.global [%0], [%1], 16;"
                         :: "r"(d), "l"((const char*)(qkvhi + gq)));
        }
    }
    auto load_kv = [&](int j, int st) {
        uint32_t stb = sb + OFF_ST + st * KVSTG;
#pragma unroll
        for (int i = 0; i < 4; i++) {
            int id = tid + i * 256;
            int row = id >> 3, col = id & 7;
            uint32_t d = stb + row * AT_ROWB + col * 16;
            size_t gk = (size_t)(j * QBLK + row) * E3 + E_DIM + h * HDIM + col * 8;
            size_t gv = gk + E_DIM;
            asm volatile("cp.async.cg.shared.global [%0], [%1], 16;"
                         :: "r"(d), "l"((const char*)(qkvhi + gk)));
            asm volatile("cp.async.cg.shared.global [%0], [%1], 16;"
                         :: "r"(d + AT_MAT), "l"((const char*)(qkvhi + gv)));
        }
    };
    load_kv(0, 0);
    asm volatile("cp.async.commit_group;");
    asm volatile("cp.async.wait_group 0;");
    __syncthreads();

    // ---- Q fragments (persistent) ----
    uint32_t qh[4][4];
    {
        uint32_t qaddr = sb + OFF_Q + (wm * 16 + rbase) * AT_ROWB + cbase;
#pragma unroll
        for (int kt = 0; kt < 4; kt++)
            ldsm4(qh[kt], qaddr + kt * 32);
    }

    float o[8][4];
#pragma unroll
    for (int nt = 0; nt < 8; nt++)
#pragma unroll
        for (int e = 0; e < 4; e++) o[nt][e] = 0.f;
    float m0 = -1e30f, m1 = -1e30f, l0 = 0.f, l1 = 0.f;

    for (int j = 0; j <= qb; ++j) {
        if (j > 0) {
            asm volatile("cp.async.wait_group 0;");
        }
        __syncthreads();
        if (j < qb) {
            load_kv(j + 1, (j + 1) & 1);
            asm volatile("cp.async.commit_group;");
        }
        const uint32_t stb = sb + OFF_ST + (j & 1) * KVSTG;

        // ---- S = Q @ K^T (1 product) ----
        float c[16][4];
#pragma unroll
        for (int nt = 0; nt < 16; nt++)
#pragma unroll
            for (int e = 0; e < 4; e++) c[nt][e] = 0.f;

#pragma unroll
        for (int kt = 0; kt < 4; kt++) {
#pragma unroll
            for (int P = 0; P < 8; P++) {
                uint32_t ka = stb + (P * 16 + krow) * AT_ROWB + kt * 32 + kcol;
                uint32_t kh[4];
                ldsm4(kh, ka);
                mma_f16(c[2 * P],     qh[kt], &kh[0]);
                mma_f16(c[2 * P + 1], qh[kt], &kh[2]);
            }
        }

        // ---- online softmax (log2 domain) ----
        float mx0 = c[0][0], mx1 = c[0][2];
#pragma unroll
        for (int nt = 0; nt < 16; nt++) {
            mx0 = fmaxf(mx0, fmaxf(c[nt][0], c[nt][1]));
            mx1 = fmaxf(mx1, fmaxf(c[nt][2], c[nt][3]));
        }
#pragma unroll
        for (int off = 1; off < 4; off <<= 1) {
            mx0 = fmaxf(mx0, __shfl_xor_sync(0xffffffffu, mx0, off));
            mx1 = fmaxf(mx1, __shfl_xor_sync(0xffffffffu, mx1, off));
        }
        float mn0 = fmaxf(m0, mx0), mn1 = fmaxf(m1, mx1);
        float a0 = ex2f(m0 - mn0), a1 = ex2f(m1 - mn1);
        m0 = mn0; m1 = mn1;
        float s0 = 0.f, s1 = 0.f;
#pragma unroll
        for (int nt = 0; nt < 16; nt++) {
            c[nt][0] = ex2f(c[nt][0] - mn0);
            c[nt][1] = ex2f(c[nt][1] - mn0);
            c[nt][2] = ex2f(c[nt][2] - mn1);
            c[nt][3] = ex2f(c[nt][3] - mn1);
            s0 += c[nt][0] + c[nt][1];
            s1 += c[nt][2] + c[nt][3];
        }
#pragma unroll
        for (int off = 1; off < 4; off <<= 1) {
            s0 += __shfl_xor_sync(0xffffffffu, s0, off);
            s1 += __shfl_xor_sync(0xffffffffu, s1, off);
        }
        l0 = l0 * a0 + s0;
        l1 = l1 * a1 + s1;
#pragma unroll
        for (int nt = 0; nt < 8; nt++) {
            o[nt][0] *= a0; o[nt][1] *= a0;
            o[nt][2] *= a1; o[nt][3] *= a1;
        }

        // ---- O += P @ V (single-term) ----
#pragma unroll
        for (int J = 0; J < 8; J++) {
            uint32_t phi[4];
#pragma unroll
            for (int q4 = 0; q4 < 2; q4++) {
#pragma unroll
                for (int rh = 0; rh < 2; rh++) {
                    phi[q4 * 2 + rh] = pack_h2(c[2 * J + q4][2 * rh],
                                               c[2 * J + q4][2 * rh + 1]);
                }
            }
#pragma unroll
            for (int pr = 0; pr < 4; pr++) {
                uint32_t va = stb + AT_MAT + (J * 16 + rbase) * AT_ROWB
                              + pr * 32 + cbase;
                uint32_t vh[4];
                ldsm4t(vh, va);
                mma_f16(o[2 * pr],     phi, &vh[0]);
                mma_f16(o[2 * pr + 1], phi, &vh[2]);
            }
        }
    }

    // ---- epilogue: normalize, fp16 ctx ----
    float inv0 = 1.f / l0, inv1 = 1.f / l1;
    const int g = lane >> 2;
    const int cp2 = (lane & 3) * 2;
    int row0 = qrow0 + wm * 16 + g;
#pragma unroll
    for (int nt = 0; nt < 8; nt++) {
        int col = h * HDIM + nt * 8 + cp2;
        *(__half2*)(chi + (size_t)row0 * E_DIM + col) =
            __halves2half2(__float2half_rn(o[nt][0] * inv0),
                           __float2half_rn(o[nt][1] * inv0));
        *(__half2*)(chi + (size_t)(row0 + 8) * E_DIM + col) =
            __halves2half2(__float2half_rn(o[nt][2] * inv1),
                           __float2half_rn(o[nt][3] * inv1));
    }
}

// ---------------------------------------------------------------------------
extern "C" void kernel_launch(void* const* d_in, const int* in_sizes, int n_in,
                              void* d_out, int out_size)
{
    const float* x     = (const float*)d_in[0];
    const float* w_in  = (const float*)d_in[1];
    const float* b_in  = (const float*)d_in[2];
    const float* w_out = (const float*)d_in[3];
    const float* b_out = (const float*)d_in[4];
    float* out = (float*)d_out;

    __half *qkvhi, *xhi, *w1hi, *w2hi, *chi;
    cudaGetSymbolAddress((void**)&qkvhi, g_qkvhi);
    cudaGetSymbolAddress((void**)&xhi,  g_xhi);
    cudaGetSymbolAddress((void**)&w1hi, g_w1hi);
    cudaGetSymbolAddress((void**)&w2hi, g_w2hi);
    cudaGetSymbolAddress((void**)&chi,  g_chi);

    cudaFuncSetAttribute((const void*)gemm_mma<true>,
                         cudaFuncAttributeMaxDynamicSharedMemorySize, GEMM_SMEM);
    cudaFuncSetAttribute((const void*)gemm_mma<false>,
                         cudaFuncAttributeMaxDynamicSharedMemorySize, GEMM_SMEM);
    cudaFuncSetAttribute(attn_mma, cudaFuncAttributeMaxDynamicSharedMemorySize, ATTN_SMEM);

    // 0) fused fp32 -> fp16 converts
    {
        int total = NX + NW1 + NW2;
        convert_all_kernel<<<(total / 4 + 255) / 256, 256>>>(x, w_in, w_out,
                                                             xhi, w1hi, w2hi);
    }

    const float qscale = 0.125f * 1.44269504088896340736f;  // (1/sqrt(64))*log2(e)

    // 1) QKV projection (1-product fp16, 4-stage) -> fp16 qkv (q cols pre-scaled)
    {
        dim3 grid(E3 / 128, S_LEN / 128);
        gemm_mma<true><<<grid, 256, GEMM_SMEM>>>(xhi, w1hi, b_in,
                                                 nullptr, qkvhi,
                                                 S_LEN, E3, E_DIM, E_DIM, qscale);
    }

    // 2) block-causal attention -> ctx fp16
    {
        dim3 grid(S_LEN / QBLK, NHEAD);
        attn_mma<<<grid, 256, ATTN_SMEM>>>(qkvhi, chi);
    }

    // 3) out projection (1-product fp16, 4-stage) -> fp32 out
    {
        dim3 grid(E_DIM / 128, S_LEN / 128);
        gemm_mma<false><<<grid, 256, GEMM_SMEM>>>(chi, w2hi, b_out,
                                                  out, nullptr,
                                                  S_LEN, E_DIM, E_DIM, 0, 1.0f);
    }
}